// round 11
// baseline (speedup 1.0000x reference)
#include <cuda_runtime.h>
#include <math.h>

// ---------------- problem constants ----------------
#define L      4096      // T*Hs*Ws = 16*16*16 tokens
#define C      192       // dim
#define DI     384       // d_inner
#define NS     16        // d_state
#define RK     12        // dt_rank
#define TT     16        // T
#define HH     64        // H
#define WW     64        // W

// ---------------- scratch (device globals; no allocation) ----------------
__device__ float g_tokens[L * C];     // (l, c) row-major
__device__ float g_norm1 [L * C];     // (l, c)
__device__ float g_xcT   [DI * L];    // (d, l)
__device__ float g_zT    [DI * L];    // (d, l)
__device__ float g_xsT   [DI * L];    // (d, l)
__device__ float g_dtinT [RK * L];    // (r, l)
__device__ float g_BT    [NS * L];    // (s, l)
__device__ float g_CT    [NS * L];    // (s, l)
__device__ float g_dtT   [DI * L];    // (d, l)  softplus applied
__device__ float g_yT    [DI * L];    // (d, l)  gated scan output
__device__ float g_y2    [L * C];     // (l, c)  after W_out
__device__ float g_norm2 [L * C];     // (l, c)
__device__ float g_weight[C];

// ---------------- 1. avg-pool 4x4 -> tokens (l, c) ----------------
__global__ __launch_bounds__(256) void k_pool(const float* __restrict__ x) {
    int c = blockIdx.x, t = blockIdx.y;
    int tid = threadIdx.x;
    int hs = tid >> 4, ws = tid & 15;
    const float* base = x + ((c * TT + t) * HH + hs * 4) * WW + ws * 4;
    float s = 0.f;
#pragma unroll
    for (int r = 0; r < 4; r++) {
        float4 v = *(const float4*)(base + r * WW);
        s += v.x + v.y + v.z + v.w;
    }
    g_tokens[(t * 256 + hs * 16 + ws) * C + c] = s * (1.f / 16.f);
}

// ---------------- 2/9. layernorm over C=192 (one warp per token) ----------------
// mode 0: out = LN(tokens) -> g_norm1 ; mode 1: out = LN(tokens + g_y2) -> g_norm2
__global__ __launch_bounds__(256) void k_ln(const float* __restrict__ gw,
                                            const float* __restrict__ bw, int mode) {
    int l = blockIdx.x * 8 + (threadIdx.x >> 5);
    int lane = threadIdx.x & 31;
    const float* p = g_tokens + l * C;
    float v[6];
    float s = 0.f, sq = 0.f;
#pragma unroll
    for (int i = 0; i < 6; i++) {
        int c = lane + 32 * i;
        float t = p[c];
        if (mode) t += g_y2[l * C + c];
        v[i] = t; s += t; sq += t * t;
    }
#pragma unroll
    for (int o = 16; o > 0; o >>= 1) {
        s  += __shfl_xor_sync(0xffffffffu, s,  o);
        sq += __shfl_xor_sync(0xffffffffu, sq, o);
    }
    float mean = s * (1.f / C);
    float var  = sq * (1.f / C) - mean * mean;
    float rstd = rsqrtf(var + 1e-5f);
    float* out = mode ? g_norm2 : g_norm1;
#pragma unroll
    for (int i = 0; i < 6; i++) {
        int c = lane + 32 * i;
        out[l * C + c] = (v[i] - mean) * rstd * gw[c] + bw[c];
    }
}

// ---------------- 3/8. tiled SGEMM, 64x64 tile, C = A * B^T ----------------
// MODE 0: A = g_norm1 (M-major, K=192), B = W_in (768,192), out split-transposed to xcT/zT
// MODE 1: A = g_yT (K-major, K=384),    B = W_out (192,384), out g_y2 row-major
template <int MODE>
__global__ __launch_bounds__(256) void k_gemm64(const float* __restrict__ Bw) {
    constexpr int K = (MODE == 0) ? 192 : 384;
    constexpr int N = (MODE == 0) ? 768 : 192;
    __shared__ float As[16][68];
    __shared__ float Bs[16][68];
    const int m0 = blockIdx.x * 64;
    const int n0 = blockIdx.y * 64;
    const int tid = threadIdx.x;
    const int tx = tid & 15, ty = tid >> 4;
    float acc[4][4] = {};
    for (int k0 = 0; k0 < K; k0 += 16) {
        if (MODE == 0) {
            int row = tid >> 2, c4 = (tid & 3) << 2;
            float4 va = *(const float4*)(g_norm1 + (m0 + row) * K + k0 + c4);
            As[c4 + 0][row] = va.x; As[c4 + 1][row] = va.y;
            As[c4 + 2][row] = va.z; As[c4 + 3][row] = va.w;
        } else {
            int kk = tid >> 4, mm = (tid & 15) << 2;
            *(float4*)&As[kk][mm] = *(const float4*)(g_yT + (k0 + kk) * L + m0 + mm);
        }
        {
            int row = tid >> 2, c4 = (tid & 3) << 2;
            float4 vb = *(const float4*)(Bw + (n0 + row) * K + k0 + c4);
            Bs[c4 + 0][row] = vb.x; Bs[c4 + 1][row] = vb.y;
            Bs[c4 + 2][row] = vb.z; Bs[c4 + 3][row] = vb.w;
        }
        __syncthreads();
#pragma unroll
        for (int kk = 0; kk < 16; kk++) {
            float4 av = *(const float4*)&As[kk][ty << 2];
            float4 bv = *(const float4*)&Bs[kk][tx << 2];
            float a[4] = {av.x, av.y, av.z, av.w};
            float b[4] = {bv.x, bv.y, bv.z, bv.w};
#pragma unroll
            for (int i = 0; i < 4; i++)
#pragma unroll
                for (int j = 0; j < 4; j++)
                    acc[i][j] = fmaf(a[i], b[j], acc[i][j]);
        }
        __syncthreads();
    }
    if (MODE == 0) {
#pragma unroll
        for (int j = 0; j < 4; j++) {
            int n = n0 + (tx << 2) + j;
            float4 v = make_float4(acc[0][j], acc[1][j], acc[2][j], acc[3][j]);
            float* dst = (n < DI) ? (g_xcT + n * L) : (g_zT + (n - DI) * L);
            *(float4*)(dst + m0 + (ty << 2)) = v;
        }
    } else {
#pragma unroll
        for (int i = 0; i < 4; i++) {
            int m = m0 + (ty << 2) + i;
            *(float4*)(g_y2 + m * N + n0 + (tx << 2)) =
                make_float4(acc[i][0], acc[i][1], acc[i][2], acc[i][3]);
        }
    }
}

// ---------------- 4. causal depthwise conv (k=4) + SiLU -> xsT ----------------
__global__ __launch_bounds__(256) void k_conv_silu(const float* __restrict__ cw,
                                                   const float* __restrict__ cb) {
    int d = blockIdx.y;
    int l = blockIdx.x * 256 + threadIdx.x;
    const float* xc = g_xcT + d * L;
    float w0 = cw[d * 4 + 0], w1 = cw[d * 4 + 1], w2 = cw[d * 4 + 2], w3 = cw[d * 4 + 3];
    float v = cb[d] + w3 * xc[l];
    if (l >= 1) v = fmaf(w2, xc[l - 1], v);
    if (l >= 2) v = fmaf(w1, xc[l - 2], v);
    if (l >= 3) v = fmaf(w0, xc[l - 3], v);
    g_xsT[d * L + l] = v / (1.f + __expf(-v));
}

// ---------------- 5. x_dbl = xs @ W_xp^T  (M=4096, N=44, K=384), transposed out ----------------
__global__ __launch_bounds__(128) void k_gemm_xp(const float* __restrict__ Wxp) {
    __shared__ float Ws[2][44][32];
    __shared__ float red[2][44][64];
    const int m0 = blockIdx.x * 64;
    const int tid = threadIdx.x;
    const int ml = tid & 63, ks = tid >> 6;  // 2 k-slices of 192
    float acc[44];
#pragma unroll
    for (int n = 0; n < 44; n++) acc[n] = 0.f;
    for (int ch = 0; ch < 6; ch++) {
        __syncthreads();
        for (int i = tid; i < 2 * 44 * 32; i += 128) {
            int ksl = i / 1408; int rr = i - ksl * 1408;
            int n = rr >> 5, kk = rr & 31;
            Ws[ksl][n][kk] = Wxp[n * 384 + ksl * 192 + ch * 32 + kk];
        }
        __syncthreads();
        int kbase = ks * 192 + ch * 32;
        for (int kk4 = 0; kk4 < 32; kk4 += 4) {
            float a0 = g_xsT[(kbase + kk4 + 0) * L + m0 + ml];
            float a1 = g_xsT[(kbase + kk4 + 1) * L + m0 + ml];
            float a2 = g_xsT[(kbase + kk4 + 2) * L + m0 + ml];
            float a3 = g_xsT[(kbase + kk4 + 3) * L + m0 + ml];
#pragma unroll
            for (int n = 0; n < 44; n++) {
                float4 w = *(const float4*)&Ws[ks][n][kk4];
                acc[n] = fmaf(a0, w.x, acc[n]);
                acc[n] = fmaf(a1, w.y, acc[n]);
                acc[n] = fmaf(a2, w.z, acc[n]);
                acc[n] = fmaf(a3, w.w, acc[n]);
            }
        }
    }
    __syncthreads();
#pragma unroll
    for (int n = 0; n < 44; n++) red[ks][n][ml] = acc[n];
    __syncthreads();
    for (int i = tid; i < 44 * 64; i += 128) {
        int n = i >> 6, mm = i & 63;
        float v = red[0][n][mm] + red[1][n][mm];
        int m = m0 + mm;
        if      (n < 12) g_dtinT[n * L + m] = v;
        else if (n < 28) g_BT[(n - 12) * L + m] = v;
        else             g_CT[(n - 28) * L + m] = v;
    }
}

// ---------------- 6. dt = softplus(x_dbl[:,:12] @ W_dt^T + b_dt) ----------------
__global__ __launch_bounds__(256) void k_dt(const float* __restrict__ Wdt,
                                            const float* __restrict__ bdt) {
    int d = blockIdx.y;
    int l = blockIdx.x * 256 + threadIdx.x;
    float s = bdt[d];
#pragma unroll
    for (int r = 0; r < RK; r++)
        s = fmaf(Wdt[d * RK + r], g_dtinT[r * L + l], s);
    float sp = (s > 20.f) ? s : log1pf(__expf(s));
    g_dtT[d * L + l] = sp;
}

// ---------------- 7. selective scan: one warp = 2 channels, lane = state ----------------
__global__ __launch_bounds__(64) void k_scan(const float* __restrict__ A_log,
                                             const float* __restrict__ Dp) {
    const int lane = threadIdx.x & 31;
    const int warp = threadIdx.x >> 5;
    const int half = lane >> 4, s = lane & 15;
    const int d = (blockIdx.x * 2 + warp) * 2 + half;
    const float* dtp = g_dtT + d * L;
    const float* xsp = g_xsT + d * L;
    const float* zp  = g_zT  + d * L;
    const float* Bp  = g_BT  + s * L;
    const float* Cp  = g_CT  + s * L;
    float* yp = g_yT + d * L;
    const float aexp = -__expf(A_log[d * NS + s]) * 1.44269504f;  // A_s * log2(e)
    const float Dd = Dp[d];
    float h = 0.f;

    float4 dt4 = *(const float4*)(dtp);
    float4 xs4 = *(const float4*)(xsp);
    float4 B4  = *(const float4*)(Bp);
    float4 C4  = *(const float4*)(Cp);

#define SCAN_STEP(DJ, XJ, BJ, CJ, YJ)                                   \
    {                                                                   \
        float dA;                                                       \
        asm("ex2.approx.ftz.f32 %0, %1;" : "=f"(dA) : "f"((DJ) * aexp));\
        float dBx = ((DJ) * (XJ)) * (BJ);                               \
        h = fmaf(dA, h, dBx);                                           \
        float cc = h * (CJ);                                            \
        cc += __shfl_xor_sync(0xffffffffu, cc, 8);                      \
        cc += __shfl_xor_sync(0xffffffffu, cc, 4);                      \
        cc += __shfl_xor_sync(0xffffffffu, cc, 2);                      \
        cc += __shfl_xor_sync(0xffffffffu, cc, 1);                      \
        YJ = cc;                                                        \
    }

#define SCAN_BODY(T)                                                    \
    {                                                                   \
        float y0, y1, y2, y3;                                           \
        SCAN_STEP(dt4.x, xs4.x, B4.x, C4.x, y0)                         \
        SCAN_STEP(dt4.y, xs4.y, B4.y, C4.y, y1)                         \
        SCAN_STEP(dt4.z, xs4.z, B4.z, C4.z, y2)                         \
        SCAN_STEP(dt4.w, xs4.w, B4.w, C4.w, y3)                         \
        if (s == 0) {                                                   \
            float4 z4 = *(const float4*)(zp + (T));                     \
            float4 o;                                                   \
            o.x = (y0 + xs4.x * Dd) * (z4.x / (1.f + __expf(-z4.x)));   \
            o.y = (y1 + xs4.y * Dd) * (z4.y / (1.f + __expf(-z4.y)));   \
            o.z = (y2 + xs4.z * Dd) * (z4.z / (1.f + __expf(-z4.z)));   \
            o.w = (y3 + xs4.w * Dd) * (z4.w / (1.f + __expf(-z4.w)));   \
            *(float4*)(yp + (T)) = o;                                   \
        }                                                               \
    }

    for (int t = 0; t < L - 4; t += 4) {
        float4 ndt = *(const float4*)(dtp + t + 4);
        float4 nxs = *(const float4*)(xsp + t + 4);
        float4 nB  = *(const float4*)(Bp + t + 4);
        float4 nC  = *(const float4*)(Cp + t + 4);
        SCAN_BODY(t)
        dt4 = ndt; xs4 = nxs; B4 = nB; C4 = nC;
    }
    SCAN_BODY(L - 4)
#undef SCAN_BODY
#undef SCAN_STEP
}

// ---------------- 10. spectral weight: pooled -> rfft mags 1..7 -> sigmoid ----------------
__global__ __launch_bounds__(256) void k_weight() {
    int c = blockIdx.x;
    int tid = threadIdx.x;
    __shared__ float pooled[TT];
    __shared__ float mg[8];
    int t = tid >> 4, j = tid & 15;
    float s = 0.f;
#pragma unroll
    for (int k = 0; k < 16; k++) {
        int sp = j + k * 16;
        s += g_norm2[(t * 256 + sp) * C + c];
    }
#pragma unroll
    for (int o = 8; o > 0; o >>= 1) s += __shfl_xor_sync(0xffffffffu, s, o);
    if (j == 0) pooled[t] = s * (1.f / 256.f);
    __syncthreads();
    if (tid < 7) {
        int k = tid + 1;
        float re = 0.f, im = 0.f;
        for (int tt = 0; tt < TT; tt++) {
            float ang = -6.2831853071795865f * (float)(k * tt) / 16.f;
            float sn, cs;
            __sincosf(ang, &sn, &cs);
            re = fmaf(pooled[tt], cs, re);
            im = fmaf(pooled[tt], sn, im);
        }
        mg[tid] = sqrtf(re * re + im * im);
    }
    __syncthreads();
    if (tid == 0) {
        float m = 0.f;
#pragma unroll
        for (int k = 0; k < 7; k++) m += mg[k];
        m *= (1.f / 7.f);
        g_weight[c] = 1.f / (1.f + __expf(-m));
    }
}

// ---------------- 11. bilinear upsample 16->64 (T identity) * sigmoid(x) ----------------
__global__ __launch_bounds__(256) void k_final(const float* __restrict__ x,
                                               float* __restrict__ out) {
    int bid = blockIdx.x;
    int c = bid % C, t = bid / C;
    __shared__ float v[16][17];
    int tid = threadIdx.x;
    float wgt = g_weight[c];
    {
        int hs = tid >> 4, ws = tid & 15;
        v[hs][ws] = g_norm2[(t * 256 + hs * 16 + ws) * C + c] * wgt;
    }
    __syncthreads();
    const float* xp = x + (c * TT + t) * (HH * WW);
    float* op = out + (c * TT + t) * (HH * WW);
#pragma unroll
    for (int i = 0; i < 16; i++) {
        int idx = tid + i * 256;
        int h = idx >> 6, w = idx & 63;
        float fy = h * 0.25f - 0.375f;
        float fx = w * 0.25f - 0.375f;
        float fy0 = floorf(fy), fx0 = floorf(fx);
        float ty = fy - fy0, tx = fx - fx0;
        int y0 = max((int)fy0, 0), y1 = min((int)fy0 + 1, 15);
        int x0 = max((int)fx0, 0), x1 = min((int)fx0 + 1, 15);
        float top = v[y0][x0] + tx * (v[y0][x1] - v[y0][x0]);
        float bot = v[y1][x0] + tx * (v[y1][x1] - v[y1][x0]);
        float up = top + ty * (bot - top);
        float xv = xp[idx];
        op[idx] = up * (1.f / (1.f + __expf(-xv)));
    }
}

// ---------------- launch ----------------
extern "C" void kernel_launch(void* const* d_in, const int* in_sizes, int n_in,
                              void* d_out, int out_size) {
    const float* x      = (const float*)d_in[0];
    const float* ln1_g  = (const float*)d_in[1];
    const float* ln1_b  = (const float*)d_in[2];
    const float* ln2_g  = (const float*)d_in[3];
    const float* ln2_b  = (const float*)d_in[4];
    const float* W_in   = (const float*)d_in[5];
    const float* conv_w = (const float*)d_in[6];
    const float* conv_b = (const float*)d_in[7];
    const float* W_xp   = (const float*)d_in[8];
    const float* W_dt   = (const float*)d_in[9];
    const float* b_dt   = (const float*)d_in[10];
    const float* A_log  = (const float*)d_in[11];
    const float* Dp     = (const float*)d_in[12];
    const float* W_out  = (const float*)d_in[13];
    float* out = (float*)d_out;

    k_pool<<<dim3(C, TT), 256>>>(x);
    k_ln<<<L / 8, 256>>>(ln1_g, ln1_b, 0);
    k_gemm64<0><<<dim3(L / 64, 768 / 64), 256>>>(W_in);
    k_conv_silu<<<dim3(L / 256, DI), 256>>>(conv_w, conv_b);
    k_gemm_xp<<<L / 64, 128>>>(W_xp);
    k_dt<<<dim3(L / 256, DI), 256>>>(W_dt, b_dt);
    k_scan<<<DI / 4, 64>>>(A_log, Dp);
    k_gemm64<1><<<dim3(L / 64, C / 64), 256>>>(W_out);
    k_ln<<<L / 8, 256>>>(ln2_g, ln2_b, 1);
    k_weight<<<C, 256>>>();
    k_final<<<C * TT, 256>>>(x, out);
}

// round 16
// speedup vs baseline: 1.0908x; 1.0908x over previous
#include <cuda_runtime.h>
#include <math.h>

// ---------------- problem constants ----------------
#define L      4096      // T*Hs*Ws = 16*16*16 tokens
#define C      192       // dim
#define DI     384       // d_inner
#define NS     16        // d_state
#define RK     12        // dt_rank
#define TT     16        // T
#define HH     64        // H
#define WW     64        // W

// ---------------- scratch (device globals; no allocation) ----------------
__device__ float g_tokens[L * C];     // (l, c) row-major
__device__ float g_norm1 [L * C];     // (l, c)
__device__ float g_xcT   [DI * L];    // (d, l)
__device__ float g_zT    [DI * L];    // (d, l)
__device__ float g_xsT   [DI * L];    // (d, l)
__device__ float g_dtinT [RK * L];    // (r, l)
__device__ float g_BT    [NS * L];    // (s, l)
__device__ float g_CT    [NS * L];    // (s, l)
__device__ float g_dtT   [DI * L];    // (d, l)  softplus applied
__device__ float g_yT    [DI * L];    // (d, l)  gated scan output
__device__ float g_y2    [L * C];     // (l, c)  after W_out
__device__ float g_norm2 [L * C];     // (l, c)
__device__ float g_weight[C];

// ---------------- 1. avg-pool 4x4 -> tokens (l, c), coalesced both ways ----------------
__global__ __launch_bounds__(256) void k_pool(const float* __restrict__ x) {
    __shared__ float buf[16][193];     // [ws][c]
    int t = blockIdx.x, hs = blockIdx.y;
    int tid = threadIdx.x;
#pragma unroll
    for (int it = 0; it < 12; it++) {
        int p = it * 256 + tid;        // 3072 (c, ws) pairs
        int c = p >> 4, ws = p & 15;
        const float* base = x + ((c * TT + t) * HH + hs * 4) * WW + ws * 4;
        float s = 0.f;
#pragma unroll
        for (int r = 0; r < 4; r++) {
            float4 v = *(const float4*)(base + r * WW);
            s += v.x + v.y + v.z + v.w;
        }
        buf[ws][c] = s * (1.f / 16.f);
    }
    __syncthreads();
    float* dst = g_tokens + (t * 256 + hs * 16) * C;   // 3072 contiguous floats
#pragma unroll
    for (int it = 0; it < 12; it++) {
        int o = it * 256 + tid;
        int ws2 = o / C, c2 = o - ws2 * C;
        dst[o] = buf[ws2][c2];
    }
}

// ---------------- 2/9. layernorm over C=192 (one warp per token) ----------------
// mode 0: out = LN(tokens) -> g_norm1 ; mode 1: out = LN(tokens + g_y2) -> g_norm2
__global__ __launch_bounds__(256) void k_ln(const float* __restrict__ gw,
                                            const float* __restrict__ bw, int mode) {
    int l = blockIdx.x * 8 + (threadIdx.x >> 5);
    int lane = threadIdx.x & 31;
    const float* p = g_tokens + l * C;
    float v[6];
    float s = 0.f, sq = 0.f;
#pragma unroll
    for (int i = 0; i < 6; i++) {
        int c = lane + 32 * i;
        float t = p[c];
        if (mode) t += g_y2[l * C + c];
        v[i] = t; s += t; sq += t * t;
    }
#pragma unroll
    for (int o = 16; o > 0; o >>= 1) {
        s  += __shfl_xor_sync(0xffffffffu, s,  o);
        sq += __shfl_xor_sync(0xffffffffu, sq, o);
    }
    float mean = s * (1.f / C);
    float var  = sq * (1.f / C) - mean * mean;
    float rstd = rsqrtf(var + 1e-5f);
    float* out = mode ? g_norm2 : g_norm1;
#pragma unroll
    for (int i = 0; i < 6; i++) {
        int c = lane + 32 * i;
        out[l * C + c] = (v[i] - mean) * rstd * gw[c] + bw[c];
    }
}

// ---------------- 3/8. tiled SGEMM, 64x64 tile, C = A * B^T ----------------
// MODE 0: A = g_norm1 (M-major, K=192), B = W_in (768,192), out split-transposed to xcT/zT
// MODE 1: A = g_yT (K-major, K=384),    B = W_out (192,384), out g_y2 row-major
template <int MODE>
__global__ __launch_bounds__(256) void k_gemm64(const float* __restrict__ Bw) {
    constexpr int K = (MODE == 0) ? 192 : 384;
    constexpr int N = (MODE == 0) ? 768 : 192;
    __shared__ float As[16][68];
    __shared__ float Bs[16][68];
    const int m0 = blockIdx.x * 64;
    const int n0 = blockIdx.y * 64;
    const int tid = threadIdx.x;
    const int tx = tid & 15, ty = tid >> 4;
    float acc[4][4] = {};
    for (int k0 = 0; k0 < K; k0 += 16) {
        if (MODE == 0) {
            int row = tid >> 2, c4 = (tid & 3) << 2;
            float4 va = *(const float4*)(g_norm1 + (m0 + row) * K + k0 + c4);
            As[c4 + 0][row] = va.x; As[c4 + 1][row] = va.y;
            As[c4 + 2][row] = va.z; As[c4 + 3][row] = va.w;
        } else {
            int kk = tid >> 4, mm = (tid & 15) << 2;
            *(float4*)&As[kk][mm] = *(const float4*)(g_yT + (k0 + kk) * L + m0 + mm);
        }
        {
            int row = tid >> 2, c4 = (tid & 3) << 2;
            float4 vb = *(const float4*)(Bw + (n0 + row) * K + k0 + c4);
            Bs[c4 + 0][row] = vb.x; Bs[c4 + 1][row] = vb.y;
            Bs[c4 + 2][row] = vb.z; Bs[c4 + 3][row] = vb.w;
        }
        __syncthreads();
#pragma unroll
        for (int kk = 0; kk < 16; kk++) {
            float4 av = *(const float4*)&As[kk][ty << 2];
            float4 bv = *(const float4*)&Bs[kk][tx << 2];
            float a[4] = {av.x, av.y, av.z, av.w};
            float b[4] = {bv.x, bv.y, bv.z, bv.w};
#pragma unroll
            for (int i = 0; i < 4; i++)
#pragma unroll
                for (int j = 0; j < 4; j++)
                    acc[i][j] = fmaf(a[i], b[j], acc[i][j]);
        }
        __syncthreads();
    }
    if (MODE == 0) {
#pragma unroll
        for (int j = 0; j < 4; j++) {
            int n = n0 + (tx << 2) + j;
            float4 v = make_float4(acc[0][j], acc[1][j], acc[2][j], acc[3][j]);
            float* dst = (n < DI) ? (g_xcT + n * L) : (g_zT + (n - DI) * L);
            *(float4*)(dst + m0 + (ty << 2)) = v;
        }
    } else {
#pragma unroll
        for (int i = 0; i < 4; i++) {
            int m = m0 + (ty << 2) + i;
            *(float4*)(g_y2 + m * N + n0 + (tx << 2)) =
                make_float4(acc[i][0], acc[i][1], acc[i][2], acc[i][3]);
        }
    }
}

// ---------------- 4. causal depthwise conv (k=4) + SiLU -> xsT ----------------
__global__ __launch_bounds__(256) void k_conv_silu(const float* __restrict__ cw,
                                                   const float* __restrict__ cb) {
    int d = blockIdx.y;
    int l = blockIdx.x * 256 + threadIdx.x;
    const float* xc = g_xcT + d * L;
    float w0 = cw[d * 4 + 0], w1 = cw[d * 4 + 1], w2 = cw[d * 4 + 2], w3 = cw[d * 4 + 3];
    float v = cb[d] + w3 * xc[l];
    if (l >= 1) v = fmaf(w2, xc[l - 1], v);
    if (l >= 2) v = fmaf(w1, xc[l - 2], v);
    if (l >= 3) v = fmaf(w0, xc[l - 3], v);
    g_xsT[d * L + l] = v / (1.f + __expf(-v));
}

// ---------------- 5. x_dbl = xs @ W_xp^T  (M=4096, N=44, K=384), transposed out ----------------
__global__ __launch_bounds__(128) void k_gemm_xp(const float* __restrict__ Wxp) {
    __shared__ float Ws[2][44][32];
    __shared__ float red[2][44][64];
    const int m0 = blockIdx.x * 64;
    const int tid = threadIdx.x;
    const int ml = tid & 63, ks = tid >> 6;  // 2 k-slices of 192
    float acc[44];
#pragma unroll
    for (int n = 0; n < 44; n++) acc[n] = 0.f;
    for (int ch = 0; ch < 6; ch++) {
        __syncthreads();
        for (int i = tid; i < 2 * 44 * 32; i += 128) {
            int ksl = i / 1408; int rr = i - ksl * 1408;
            int n = rr >> 5, kk = rr & 31;
            Ws[ksl][n][kk] = Wxp[n * 384 + ksl * 192 + ch * 32 + kk];
        }
        __syncthreads();
        int kbase = ks * 192 + ch * 32;
        for (int kk4 = 0; kk4 < 32; kk4 += 4) {
            float a0 = g_xsT[(kbase + kk4 + 0) * L + m0 + ml];
            float a1 = g_xsT[(kbase + kk4 + 1) * L + m0 + ml];
            float a2 = g_xsT[(kbase + kk4 + 2) * L + m0 + ml];
            float a3 = g_xsT[(kbase + kk4 + 3) * L + m0 + ml];
#pragma unroll
            for (int n = 0; n < 44; n++) {
                float4 w = *(const float4*)&Ws[ks][n][kk4];
                acc[n] = fmaf(a0, w.x, acc[n]);
                acc[n] = fmaf(a1, w.y, acc[n]);
                acc[n] = fmaf(a2, w.z, acc[n]);
                acc[n] = fmaf(a3, w.w, acc[n]);
            }
        }
    }
    __syncthreads();
#pragma unroll
    for (int n = 0; n < 44; n++) red[ks][n][ml] = acc[n];
    __syncthreads();
    for (int i = tid; i < 44 * 64; i += 128) {
        int n = i >> 6, mm = i & 63;
        float v = red[0][n][mm] + red[1][n][mm];
        int m = m0 + mm;
        if      (n < 12) g_dtinT[n * L + m] = v;
        else if (n < 28) g_BT[(n - 12) * L + m] = v;
        else             g_CT[(n - 28) * L + m] = v;
    }
}

// ---------------- 6. dt = softplus(x_dbl[:,:12] @ W_dt^T + b_dt) ----------------
__global__ __launch_bounds__(256) void k_dt(const float* __restrict__ Wdt,
                                            const float* __restrict__ bdt) {
    int d = blockIdx.y;
    int l = blockIdx.x * 256 + threadIdx.x;
    float s = bdt[d];
#pragma unroll
    for (int r = 0; r < RK; r++)
        s = fmaf(Wdt[d * RK + r], g_dtinT[r * L + l], s);
    float sp = (s > 20.f) ? s : log1pf(__expf(s));
    g_dtT[d * L + l] = sp;
}

// ---------------- 7. selective scan: 8 steps/body, interleaved shfl reductions ----------------
__global__ __launch_bounds__(64) void k_scan(const float* __restrict__ A_log,
                                             const float* __restrict__ Dp) {
    const int lane = threadIdx.x & 31;
    const int warp = threadIdx.x >> 5;
    const int half = lane >> 4, s = lane & 15;
    const int d = (blockIdx.x * 2 + warp) * 2 + half;
    const float* dtp = g_dtT + d * L;
    const float* xsp = g_xsT + d * L;
    const float* zp  = g_zT  + d * L;
    const float* Bp  = g_BT  + s * L;
    const float* Cp  = g_CT  + s * L;
    float* yp = g_yT + d * L;
    const float aexp = -__expf(A_log[d * NS + s]) * 1.44269504f;  // A_s * log2(e)
    const float Dd = Dp[d];
    float h = 0.f;

    float dt[8], xs[8], Bv[8], Cv[8];
    float ndt[8], nxs[8], nB[8], nC[8];
    *(float4*)(dt)     = *(const float4*)(dtp);
    *(float4*)(dt + 4) = *(const float4*)(dtp + 4);
    *(float4*)(xs)     = *(const float4*)(xsp);
    *(float4*)(xs + 4) = *(const float4*)(xsp + 4);
    *(float4*)(Bv)     = *(const float4*)(Bp);
    *(float4*)(Bv + 4) = *(const float4*)(Bp + 4);
    *(float4*)(Cv)     = *(const float4*)(Cp);
    *(float4*)(Cv + 4) = *(const float4*)(Cp + 4);

    for (int t = 0; t < L; t += 8) {
        // prefetch next body
        if (t + 8 < L) {
            *(float4*)(ndt)     = *(const float4*)(dtp + t + 8);
            *(float4*)(ndt + 4) = *(const float4*)(dtp + t + 12);
            *(float4*)(nxs)     = *(const float4*)(xsp + t + 8);
            *(float4*)(nxs + 4) = *(const float4*)(xsp + t + 12);
            *(float4*)(nB)      = *(const float4*)(Bp + t + 8);
            *(float4*)(nB + 4)  = *(const float4*)(Bp + t + 12);
            *(float4*)(nC)      = *(const float4*)(Cp + t + 8);
            *(float4*)(nC + 4)  = *(const float4*)(Cp + t + 12);
        }
        // phase 1: dA (independent ex2), serial h chain, per-step products
        float dA[8], cc[8];
#pragma unroll
        for (int j = 0; j < 8; j++)
            asm("ex2.approx.ftz.f32 %0, %1;" : "=f"(dA[j]) : "f"(dt[j] * aexp));
#pragma unroll
        for (int j = 0; j < 8; j++) {
            float dBx = (dt[j] * xs[j]) * Bv[j];
            h = fmaf(dA[j], h, dBx);
            cc[j] = h * Cv[j];
        }
        // phase 2: 8 independent butterfly chains, interleaved by construction
#pragma unroll
        for (int o = 8; o > 0; o >>= 1) {
#pragma unroll
            for (int j = 0; j < 8; j++)
                cc[j] += __shfl_xor_sync(0xffffffffu, cc[j], o);
        }
        // phase 3: gate + store (lane s==0 of each half)
        if (s == 0) {
            float4 z4a = *(const float4*)(zp + t);
            float4 z4b = *(const float4*)(zp + t + 4);
            float4 oa, ob;
            oa.x = (cc[0] + xs[0] * Dd) * (z4a.x / (1.f + __expf(-z4a.x)));
            oa.y = (cc[1] + xs[1] * Dd) * (z4a.y / (1.f + __expf(-z4a.y)));
            oa.z = (cc[2] + xs[2] * Dd) * (z4a.z / (1.f + __expf(-z4a.z)));
            oa.w = (cc[3] + xs[3] * Dd) * (z4a.w / (1.f + __expf(-z4a.w)));
            ob.x = (cc[4] + xs[4] * Dd) * (z4b.x / (1.f + __expf(-z4b.x)));
            ob.y = (cc[5] + xs[5] * Dd) * (z4b.y / (1.f + __expf(-z4b.y)));
            ob.z = (cc[6] + xs[6] * Dd) * (z4b.z / (1.f + __expf(-z4b.z)));
            ob.w = (cc[7] + xs[7] * Dd) * (z4b.w / (1.f + __expf(-z4b.w)));
            *(float4*)(yp + t)     = oa;
            *(float4*)(yp + t + 4) = ob;
        }
#pragma unroll
        for (int j = 0; j < 8; j++) {
            dt[j] = ndt[j]; xs[j] = nxs[j]; Bv[j] = nB[j]; Cv[j] = nC[j];
        }
    }
}

// ---------------- 10. spectral weight: pooled -> rfft mags 1..7 -> sigmoid ----------------
__global__ __launch_bounds__(256) void k_weight() {
    int c = blockIdx.x;
    int tid = threadIdx.x;
    __shared__ float pooled[TT];
    __shared__ float mg[8];
    int t = tid >> 4, j = tid & 15;
    float s = 0.f;
#pragma unroll
    for (int k = 0; k < 16; k++) {
        int sp = j + k * 16;
        s += g_norm2[(t * 256 + sp) * C + c];
    }
#pragma unroll
    for (int o = 8; o > 0; o >>= 1) s += __shfl_xor_sync(0xffffffffu, s, o);
    if (j == 0) pooled[t] = s * (1.f / 256.f);
    __syncthreads();
    if (tid < 7) {
        int k = tid + 1;
        float re = 0.f, im = 0.f;
        for (int tt = 0; tt < TT; tt++) {
            float ang = -6.2831853071795865f * (float)(k * tt) / 16.f;
            float sn, cs;
            __sincosf(ang, &sn, &cs);
            re = fmaf(pooled[tt], cs, re);
            im = fmaf(pooled[tt], sn, im);
        }
        mg[tid] = sqrtf(re * re + im * im);
    }
    __syncthreads();
    if (tid == 0) {
        float m = 0.f;
#pragma unroll
        for (int k = 0; k < 7; k++) m += mg[k];
        m *= (1.f / 7.f);
        g_weight[c] = 1.f / (1.f + __expf(-m));
    }
}

// ---------------- 11. bilinear upsample 16->64 (T identity) * sigmoid(x), float4 ----------------
__global__ __launch_bounds__(256) void k_final(const float* __restrict__ x,
                                               float* __restrict__ out) {
    int bid = blockIdx.x;
    int c = bid % C, t = bid / C;
    __shared__ float v[16][17];
    int tid = threadIdx.x;
    float wgt = g_weight[c];
    {
        int hs = tid >> 4, ws = tid & 15;
        v[hs][ws] = g_norm2[(t * 256 + hs * 16 + ws) * C + c] * wgt;
    }
    __syncthreads();
    const float* xp = x + (c * TT + t) * (HH * WW);
    float* op = out + (c * TT + t) * (HH * WW);
#pragma unroll
    for (int i = 0; i < 4; i++) {
        int e = (tid + i * 256) * 4;
        int hh = e >> 6, w0e = e & 63;
        float fy = hh * 0.25f - 0.375f;
        float fy0 = floorf(fy);
        float ty = fy - fy0;
        int y0 = max((int)fy0, 0), y1 = min((int)fy0 + 1, 15);
        float4 xv = *(const float4*)(xp + e);
        float4 ov;
        float res[4];
#pragma unroll
        for (int k = 0; k < 4; k++) {
            int w = w0e + k;
            float fx = w * 0.25f - 0.375f;
            float fx0 = floorf(fx);
            float tx = fx - fx0;
            int x0 = max((int)fx0, 0), x1 = min((int)fx0 + 1, 15);
            float top = v[y0][x0] + tx * (v[y0][x1] - v[y0][x0]);
            float bot = v[y1][x0] + tx * (v[y1][x1] - v[y1][x0]);
            res[k] = top + ty * (bot - top);
        }
        ov.x = res[0] * (1.f / (1.f + __expf(-xv.x)));
        ov.y = res[1] * (1.f / (1.f + __expf(-xv.y)));
        ov.z = res[2] * (1.f / (1.f + __expf(-xv.z)));
        ov.w = res[3] * (1.f / (1.f + __expf(-xv.w)));
        *(float4*)(op + e) = ov;
    }
}

// ---------------- launch ----------------
extern "C" void kernel_launch(void* const* d_in, const int* in_sizes, int n_in,
                              void* d_out, int out_size) {
    const float* x      = (const float*)d_in[0];
    const float* ln1_g  = (const float*)d_in[1];
    const float* ln1_b  = (const float*)d_in[2];
    const float* ln2_g  = (const float*)d_in[3];
    const float* ln2_b  = (const float*)d_in[4];
    const float* W_in   = (const float*)d_in[5];
    const float* conv_w = (const float*)d_in[6];
    const float* conv_b = (const float*)d_in[7];
    const float* W_xp   = (const float*)d_in[8];
    const float* W_dt   = (const float*)d_in[9];
    const float* b_dt   = (const float*)d_in[10];
    const float* A_log  = (const float*)d_in[11];
    const float* Dp     = (const float*)d_in[12];
    const float* W_out  = (const float*)d_in[13];
    float* out = (float*)d_out;

    k_pool<<<dim3(TT, 16), 256>>>(x);
    k_ln<<<L / 8, 256>>>(ln1_g, ln1_b, 0);
    k_gemm64<0><<<dim3(L / 64, 768 / 64), 256>>>(W_in);
    k_conv_silu<<<dim3(L / 256, DI), 256>>>(conv_w, conv_b);
    k_gemm_xp<<<L / 64, 128>>>(W_xp);
    k_dt<<<dim3(L / 256, DI), 256>>>(W_dt, b_dt);
    k_scan<<<DI / 4, 64>>>(A_log, Dp);
    k_gemm64<1><<<dim3(L / 64, C / 64), 256>>>(W_out);
    k_ln<<<L / 8, 256>>>(ln2_g, ln2_b, 1);
    k_weight<<<C, 256>>>();
    k_final<<<C * TT, 256>>>(x, out);
}